// round 14
// baseline (speedup 1.0000x reference)
#include <cuda_runtime.h>
#include <math.h>

#define B_DIM 4096
#define K_DIM 512
#define T_DIM 30
#define WPS   4                     // warps per sample
#define CPL   (K_DIM / (32 * WPS))  // 4 candidates per lane
#define SPC   2                     // samples per CTA
#define NTH   256
#define WGRID (B_DIM / SPC)         // 2048 worker CTAs
#define GRID_TOTAL (WGRID + 1)      // +1 publisher CTA
#define MAX_GUESSES 6
#define MISS_THRESH 2.0f

// Scratch (device globals; zero at module load, reset by the publisher CTA
// each run -> deterministic across graph replays).
__device__ float        g_acc = 0.0f;
__device__ unsigned int g_cnt = 0;

// monotone float->u32 transform (total order preserved)
__device__ __forceinline__ unsigned sortable(float x) {
    unsigned u = __float_as_uint(x);
    return u ^ (unsigned)(((int)u >> 31) | 0x80000000);
}

__global__ __launch_bounds__(NTH)
void score_classify_fused(const float* __restrict__ out_scores,   // [B*K,1]
                          const float* __restrict__ pred_cand,    // [B,K,T,2]
                          const float* __restrict__ pred_gt,      // [B,T,2]
                          const float* __restrict__ scales,       // [B]
                          float* __restrict__ out)
{
    // ---- publisher CTA: spin on the release/acquire flag, publish, reset ----
    if (blockIdx.x == WGRID) {
        if (threadIdx.x == 0) {
            unsigned c;
            do {
                asm volatile("ld.acquire.gpu.global.u32 %0, [%1];"
                             : "=r"(c) : "l"(&g_cnt) : "memory");
                if (c != (unsigned)WGRID) __nanosleep(128);
            } while (c != (unsigned)WGRID);
            out[0] = *((volatile float*)&g_acc);   // acquire orders this read
            g_acc  = 0.0f;                         // reset for next replay
            asm volatile("st.relaxed.gpu.global.u32 [%0], 0;"
                         :: "l"(&g_cnt) : "memory");
        }
        return;
    }

    const int lane = threadIdx.x & 31;
    const int wid  = threadIdx.x >> 5;     // 0..7
    const int s    = wid / WPS;            // sample slot in CTA (0..1)
    const int ws   = wid % WPS;            // warp index within sample (0..3)
    const int b    = blockIdx.x * SPC + s;

    __shared__ float    sm_sum[SPC][WPS][3];           // zs, zo, ss partials
    __shared__ unsigned sm_top[SPC][WPS][MAX_GUESSES]; // per-warp top-6 (desc)
    __shared__ unsigned sm_minf[SPC][WPS];             // per-warp min fde bits

    // per-sample constants (warp-uniform -> broadcast)
    const float2 g  = *reinterpret_cast<const float2*>(
        pred_gt + ((size_t)b * T_DIM + (T_DIM - 1)) * 2);
    const float  sc = scales[b];
    const float* ob = out_scores + (size_t)b * K_DIM;
    const float* cb = pred_cand + (((size_t)b * K_DIM) * T_DIM + (T_DIM - 1)) * 2;

    // ---- front-batched loads: 4 strided float2 gathers + 4 coalesced ----
    // Evict-first (.cs): single-use data, keep it out of L2 victim space.
    float2 c[CPL];
    float  o[CPL];
    #pragma unroll
    for (int j = 0; j < CPL; j++) {
        const int k = (ws * CPL + j) * 32 + lane;
        o[j] = __ldcs(ob + k);
        c[j] = __ldcs(reinterpret_cast<const float2*>(cb + (size_t)k * (T_DIM * 2)));
    }

    // ---- fde + exp partial sums (no max-shift: -f<=0, |o| small) ----
    float    f[CPL];
    unsigned os[CPL];
    float zs = 0.f, zo = 0.f, ss = 0.f;
    #pragma unroll
    for (int j = 0; j < CPL; j++) {
        const float dx = c[j].x - g.x;
        const float dy = c[j].y - g.y;
        f[j] = sc * sqrtf(fmaf(dx, dx, dy * dy));
        const float ef = expf(-f[j]);
        zs += ef;
        ss  = fmaf(ef, o[j], ss);
        zo += expf(o[j]);
        os[j] = sortable(o[j]);
    }

    // warp partial sums (fused butterfly), lane0 -> smem
    #pragma unroll
    for (int off = 16; off; off >>= 1) {
        zs += __shfl_xor_sync(0xffffffffu, zs, off);
        zo += __shfl_xor_sync(0xffffffffu, zo, off);
        ss += __shfl_xor_sync(0xffffffffu, ss, off);
    }
    if (lane == 0) {
        sm_sum[s][ws][0] = zs; sm_sum[s][ws][1] = zo; sm_sum[s][ws][2] = ss;
    }

    // ---- lane-local sorted list (desc) of this lane's 4 values ----
    unsigned t0 = 0, t1 = 0, t2 = 0, t3 = 0;
    #pragma unroll
    for (int j = 0; j < CPL; j++) {
        unsigned x = os[j], a;
        a = max(t0, x); x = min(t0, x); t0 = a;
        a = max(t1, x); x = min(t1, x); t1 = a;
        a = max(t2, x); x = min(t2, x); t2 = a;
        t3 = max(t3, x);
    }

    // ---- 6 warp pops via REDUX -> this warp's top-6 (desc) ----
    #pragma unroll
    for (int r = 0; r < MAX_GUESSES; r++) {
        const unsigned m = __reduce_max_sync(0xffffffffu, t0);
        if (lane == 0) sm_top[s][ws][r] = m;
        if (t0 == m) { t0 = t1; t1 = t2; t2 = t3; t3 = 0; }
    }
    __syncthreads();

    // ---- merge 4 warps' top-6 lists -> theta = 6th largest of sample ----
    unsigned m0 = 0, m1 = 0, m2 = 0, m3 = 0, m4 = 0, m5 = 0;
    #pragma unroll
    for (int w = 0; w < WPS; w++) {
        #pragma unroll
        for (int r = 0; r < MAX_GUESSES; r++) {
            unsigned x = sm_top[s][w][r], a;
            a = max(m0, x); x = min(m0, x); m0 = a;
            a = max(m1, x); x = min(m1, x); m1 = a;
            a = max(m2, x); x = min(m2, x); m2 = a;
            a = max(m3, x); x = min(m3, x); m3 = a;
            a = max(m4, x); x = min(m4, x); m4 = a;
            m5 = max(m5, x);
        }
    }
    const unsigned theta = m5;

    // ---- per-warp minFDE among {os >= theta}; f>=0 so raw bits order ----
    float minf = 3.4e38f;
    #pragma unroll
    for (int j = 0; j < CPL; j++)
        if (os[j] >= theta) minf = fminf(minf, f[j]);
    const unsigned mfb = __reduce_min_sync(0xffffffffu, __float_as_uint(minf));
    if (lane == 0) sm_minf[s][ws] = mfb;
    __syncthreads();

    // ---- per-sample value adds: relaxed no-return REDs only ----
    if (ws == 0 && lane == 0) {
        float Zs = 0.f, Zo = 0.f, Ss = 0.f;
        unsigned mn = 0xffffffffu;
        #pragma unroll
        for (int w = 0; w < WPS; w++) {
            Zs += sm_sum[s][w][0];
            Zo += sm_sum[s][w][1];
            Ss += sm_sum[s][w][2];
            mn  = min(mn, sm_minf[s][w]);
        }
        const float minF = __uint_as_float(mn);
        const float cls  = logf(Zo) - Ss / Zs;
        const float loss = cls + fmaxf(minF - MISS_THRESH, 0.0f);
        atomicAdd(&g_acc, loss * (1.0f / (float)B_DIM));   // RED.ADD (relaxed)
    }

    // ---- ONE release per CTA: barrier gives intra-CTA happens-before, so
    //      this release publishes both samples' value-adds to the acquirer ----
    __syncthreads();
    if (threadIdx.x == 0) {
        asm volatile("red.release.gpu.global.add.u32 [%0], 1;"
                     :: "l"(&g_cnt) : "memory");
    }
}

extern "C" void kernel_launch(void* const* d_in, const int* in_sizes, int n_in,
                              void* d_out, int out_size)
{
    const float* out_scores = (const float*)d_in[0];   // (B*K, 1)
    const float* pred_cand  = (const float*)d_in[1];   // (B, K, T, 2)
    const float* pred_gt    = (const float*)d_in[2];   // (B, T, 2)
    const float* scales     = (const float*)d_in[3];   // (B,)
    float* out = (float*)d_out;

    score_classify_fused<<<GRID_TOTAL, NTH>>>(out_scores, pred_cand, pred_gt,
                                              scales, out);
}

// round 15
// speedup vs baseline: 1.0365x; 1.0365x over previous
#include <cuda_runtime.h>
#include <math.h>

#define B_DIM 4096
#define K_DIM 512
#define T_DIM 30
#define WPS   4                     // warps per sample
#define CPL   (K_DIM / (32 * WPS))  // 4 candidates per lane
#define SPC   2                     // samples per CTA
#define NTH   256
#define WGRID (B_DIM / SPC)         // 2048 worker CTAs
#define GRID_TOTAL (WGRID + 1)      // +1 publisher CTA
#define MAX_GUESSES 6
#define MISS_THRESH 2.0f

// Scratch (device globals; zero at module load, reset by the publisher CTA
// each run -> deterministic across graph replays).
__device__ float        g_acc = 0.0f;
__device__ unsigned int g_cnt = 0;

// monotone float->u32 transform (total order preserved)
__device__ __forceinline__ unsigned sortable(float x) {
    unsigned u = __float_as_uint(x);
    return u ^ (unsigned)(((int)u >> 31) | 0x80000000);
}

__global__ __launch_bounds__(NTH)
void score_classify_fused(const float* __restrict__ out_scores,   // [B*K,1]
                          const float* __restrict__ pred_cand,    // [B,K,T,2]
                          const float* __restrict__ pred_gt,      // [B,T,2]
                          const float* __restrict__ scales,       // [B]
                          float* __restrict__ out)
{
    // ---- publisher CTA: spin on the release/acquire flag, publish, reset ----
    if (blockIdx.x == WGRID) {
        if (threadIdx.x == 0) {
            unsigned c;
            do {
                asm volatile("ld.acquire.gpu.global.u32 %0, [%1];"
                             : "=r"(c) : "l"(&g_cnt) : "memory");
                if (c != (unsigned)B_DIM) __nanosleep(128);
            } while (c != (unsigned)B_DIM);
            out[0] = *((volatile float*)&g_acc);   // acquire orders this read
            g_acc  = 0.0f;                         // reset for next replay
            asm volatile("st.relaxed.gpu.global.u32 [%0], 0;"
                         :: "l"(&g_cnt) : "memory");
        }
        return;
    }

    const int lane = threadIdx.x & 31;
    const int wid  = threadIdx.x >> 5;     // 0..7
    const int s    = wid / WPS;            // sample slot in CTA (0..1)
    const int ws   = wid % WPS;            // warp index within sample (0..3)
    const int b    = blockIdx.x * SPC + s;

    __shared__ float    sm_sum[SPC][WPS][3];           // zs, zo, ss partials
    __shared__ unsigned sm_top[SPC][WPS][MAX_GUESSES]; // per-warp top-6 (desc)
    __shared__ unsigned sm_minf[SPC][WPS];             // per-warp min fde bits

    // per-sample constants (warp-uniform -> broadcast)
    const float2 g  = *reinterpret_cast<const float2*>(
        pred_gt + ((size_t)b * T_DIM + (T_DIM - 1)) * 2);
    const float  sc = scales[b];
    const float* ob = out_scores + (size_t)b * K_DIM;
    const float* cb = pred_cand + (((size_t)b * K_DIM) * T_DIM + (T_DIM - 1)) * 2;

    // ---- front-batched loads: 4 strided float2 gathers + 4 coalesced ----
    // Evict-first (.cs): single-use data, keep it out of L2 victim space.
    float2 c[CPL];
    float  o[CPL];
    #pragma unroll
    for (int j = 0; j < CPL; j++) {
        const int k = (ws * CPL + j) * 32 + lane;
        o[j] = __ldcs(ob + k);
        c[j] = __ldcs(reinterpret_cast<const float2*>(cb + (size_t)k * (T_DIM * 2)));
    }

    // ---- fde + exp partial sums (no max-shift: -f<=0, |o| small) ----
    float    f[CPL];
    unsigned os[CPL];
    float zs = 0.f, zo = 0.f, ss = 0.f;
    #pragma unroll
    for (int j = 0; j < CPL; j++) {
        const float dx = c[j].x - g.x;
        const float dy = c[j].y - g.y;
        f[j] = sc * sqrtf(fmaf(dx, dx, dy * dy));
        const float ef = expf(-f[j]);
        zs += ef;
        ss  = fmaf(ef, o[j], ss);
        zo += expf(o[j]);
        os[j] = sortable(o[j]);
    }

    // warp partial sums (fused butterfly), lane0 -> smem
    #pragma unroll
    for (int off = 16; off; off >>= 1) {
        zs += __shfl_xor_sync(0xffffffffu, zs, off);
        zo += __shfl_xor_sync(0xffffffffu, zo, off);
        ss += __shfl_xor_sync(0xffffffffu, ss, off);
    }
    if (lane == 0) {
        sm_sum[s][ws][0] = zs; sm_sum[s][ws][1] = zo; sm_sum[s][ws][2] = ss;
    }

    // ---- lane-local sorted list (desc) of this lane's 4 values ----
    unsigned t0 = 0, t1 = 0, t2 = 0, t3 = 0;
    #pragma unroll
    for (int j = 0; j < CPL; j++) {
        unsigned x = os[j], a;
        a = max(t0, x); x = min(t0, x); t0 = a;
        a = max(t1, x); x = min(t1, x); t1 = a;
        a = max(t2, x); x = min(t2, x); t2 = a;
        t3 = max(t3, x);
    }

    // ---- 6 warp pops via REDUX -> this warp's top-6 (desc) ----
    #pragma unroll
    for (int r = 0; r < MAX_GUESSES; r++) {
        const unsigned m = __reduce_max_sync(0xffffffffu, t0);
        if (lane == 0) sm_top[s][ws][r] = m;
        if (t0 == m) { t0 = t1; t1 = t2; t2 = t3; t3 = 0; }
    }
    __syncthreads();

    // ---- merge 4 warps' top-6 lists -> theta = 6th largest of sample ----
    unsigned m0 = 0, m1 = 0, m2 = 0, m3 = 0, m4 = 0, m5 = 0;
    #pragma unroll
    for (int w = 0; w < WPS; w++) {
        #pragma unroll
        for (int r = 0; r < MAX_GUESSES; r++) {
            unsigned x = sm_top[s][w][r], a;
            a = max(m0, x); x = min(m0, x); m0 = a;
            a = max(m1, x); x = min(m1, x); m1 = a;
            a = max(m2, x); x = min(m2, x); m2 = a;
            a = max(m3, x); x = min(m3, x); m3 = a;
            a = max(m4, x); x = min(m4, x); m4 = a;
            m5 = max(m5, x);
        }
    }
    const unsigned theta = m5;

    // ---- per-warp minFDE among {os >= theta}; f>=0 so raw bits order ----
    float minf = 3.4e38f;
    #pragma unroll
    for (int j = 0; j < CPL; j++)
        if (os[j] >= theta) minf = fminf(minf, f[j]);
    const unsigned mfb = __reduce_min_sync(0xffffffffu, __float_as_uint(minf));
    if (lane == 0) sm_minf[s][ws] = mfb;
    __syncthreads();

    // ---- per-sample epilogue: two no-return REDs (relaxed value, release
    //      count). The publisher CTA's acquire-poll pairs with the release ----
    if (ws == 0 && lane == 0) {
        float Zs = 0.f, Zo = 0.f, Ss = 0.f;
        unsigned mn = 0xffffffffu;
        #pragma unroll
        for (int w = 0; w < WPS; w++) {
            Zs += sm_sum[s][w][0];
            Zo += sm_sum[s][w][1];
            Ss += sm_sum[s][w][2];
            mn  = min(mn, sm_minf[s][w]);
        }
        const float minF = __uint_as_float(mn);
        const float cls  = logf(Zo) - Ss / Zs;
        const float loss = cls + fmaxf(minF - MISS_THRESH, 0.0f);

        atomicAdd(&g_acc, loss * (1.0f / (float)B_DIM));   // RED.ADD (relaxed)
        asm volatile("red.release.gpu.global.add.u32 [%0], 1;"
                     :: "l"(&g_cnt) : "memory");           // RED.ADD (release)
    }
}

extern "C" void kernel_launch(void* const* d_in, const int* in_sizes, int n_in,
                              void* d_out, int out_size)
{
    const float* out_scores = (const float*)d_in[0];   // (B*K, 1)
    const float* pred_cand  = (const float*)d_in[1];   // (B, K, T, 2)
    const float* pred_gt    = (const float*)d_in[2];   // (B, T, 2)
    const float* scales     = (const float*)d_in[3];   // (B,)
    float* out = (float*)d_out;

    score_classify_fused<<<GRID_TOTAL, NTH>>>(out_scores, pred_cand, pred_gt,
                                              scales, out);
}